// round 14
// baseline (speedup 1.0000x reference)
#include <cuda_runtime.h>
#include <cstdint>

#define BSZ 4
#define TT  1024
#define DM  1024
#define HH  16
#define DK  64
#define KPAD 20
#define STG (128 * KPAD)
#define KB 68
#define QK_SMEM (2 * 128 * KB * 4)

// ---- device scratch (alloc-free rule: __device__ globals) ----
__device__ float g_qh[BSZ * TT * DM];              // (b, t, h, d)
__device__ float g_kh[BSZ * TT * DM];              // (b, h, t, d)
__device__ float g_vt[BSZ * TT * DM];              // (b, h, d, t)
__device__ float g_p[TT * DM];                     // (h, t, d)
__device__ float g_bd[67108864];                   // SHIFTED bd (b,h,t,s)
__device__ float g_concat[BSZ * TT * DM];          // (b, t, h*d)
__device__ float2 g_part[BSZ * HH * TT * 8];       // per-(row, colTile) (max, sumexp)
__device__ float2 g_ms[BSZ * HH * TT];             // per-row (max, 1/sum)

// ---------------------------------------------------------------
__device__ __forceinline__ float to_tf32(float x) {
    uint32_t u;
    asm("cvt.rna.tf32.f32 %0, %1;" : "=r"(u) : "f"(x));
    return __uint_as_float(u);
}
__device__ __forceinline__ uint32_t tf32u(float x) {
    uint32_t u;
    asm("cvt.rna.tf32.f32 %0, %1;" : "=r"(u) : "f"(x));
    return u;
}

__device__ __forceinline__ void mma8(float4& d, const uint32_t a[4], const uint32_t b[2]) {
    asm volatile(
        "mma.sync.aligned.m16n8k8.row.col.f32.tf32.tf32.f32 "
        "{%0,%1,%2,%3}, {%4,%5,%6,%7}, {%8,%9}, {%0,%1,%2,%3};\n"
        : "+f"(d.x), "+f"(d.y), "+f"(d.z), "+f"(d.w)
        : "r"(a[0]), "r"(a[1]), "r"(a[2]), "r"(a[3]), "r"(b[0]), "r"(b[1]));
}

__device__ __forceinline__ void cpa16(uint32_t saddr, const float* g) {
    asm volatile("cp.async.ca.shared.global [%0], [%1], 16;\n" :: "r"(saddr), "l"(g));
}
__device__ __forceinline__ void cp_commit() {
    asm volatile("cp.async.commit_group;\n");
}
template <int N>
__device__ __forceinline__ void cp_wait() {
    asm volatile("cp.async.wait_group %0;\n" :: "n"(N));
}

struct QKVArgs {
    const float* A[3];
    const float* B[3];
    const float* bias[3];
    float* C[3];
};

// ======================================================================
// Pipelined tensor-core NT GEMM — 256-thread (best measured)
// ======================================================================
__global__ __launch_bounds__(256, 2) void gemm_pipe(QKVArgs args, int K, int mode_sel)
{
    __shared__ __align__(16) float As[2 * STG];
    __shared__ __align__(16) float Bs[2 * STG];
    int z = blockIdx.z;
    int mode = (mode_sel >= 0) ? mode_sel : z;
    const float* A = args.A[z];
    const float* B = args.B[z];
    const float* bias = args.bias[z];
    float* C = args.C[z];
    bool has_bias = (bias != nullptr);

    int tid = threadIdx.x;
    int M0 = blockIdx.y * 128, N0 = blockIdx.x * 128;
    int w = tid >> 5, lane = tid & 31;
    int wm = w & 3, wn = w >> 2;
    int r = tid >> 2, c4 = (tid & 3) * 4;

    float4 acc[2][8];
#pragma unroll
    for (int i = 0; i < 2; i++)
#pragma unroll
        for (int j = 0; j < 8; j++) acc[i][j] = make_float4(0.f, 0.f, 0.f, 0.f);

    const float* Ag = A + (size_t)(M0 + r) * K + c4;
    const float* Bg = B + (size_t)(N0 + r) * K + c4;
    uint32_t sA = (uint32_t)__cvta_generic_to_shared(As);
    uint32_t sB = (uint32_t)__cvta_generic_to_shared(Bs);
    uint32_t offA0 = (r * KPAD + c4) * 4;
    uint32_t offA1 = ((r + 64) * KPAD + c4) * 4;

    cpa16(sA + offA0, Ag);
    cpa16(sA + offA1, Ag + (size_t)64 * K);
    cpa16(sB + offA0, Bg);
    cpa16(sB + offA1, Bg + (size_t)64 * K);
    cp_commit();

    int KT = K >> 4;
    for (int kt = 0; kt < KT; kt++) {
        if (kt + 1 < KT) {
            int st = (kt + 1) & 1;
            int k0 = (kt + 1) << 4;
            cpa16(sA + st * STG * 4 + offA0, Ag + k0);
            cpa16(sA + st * STG * 4 + offA1, Ag + (size_t)64 * K + k0);
            cpa16(sB + st * STG * 4 + offA0, Bg + k0);
            cpa16(sB + st * STG * 4 + offA1, Bg + (size_t)64 * K + k0);
            cp_commit();
            cp_wait<1>();
        } else {
            cp_wait<0>();
        }
        __syncthreads();
        const float* as = As + (kt & 1) * STG;
        const float* bs = Bs + (kt & 1) * STG;
#pragma unroll
        for (int ks = 0; ks < 16; ks += 8) {
            uint32_t bf[8][2];
#pragma unroll
            for (int nt = 0; nt < 8; nt++) {
                int nb = wn * 64 + nt * 8 + (lane >> 2);
                bf[nt][0] = tf32u(bs[nb * KPAD + ks + (lane & 3)]);
                bf[nt][1] = tf32u(bs[nb * KPAD + ks + (lane & 3) + 4]);
            }
#pragma unroll
            for (int mt = 0; mt < 2; mt++) {
                int mb = wm * 32 + mt * 16 + (lane >> 2);
                uint32_t af[4];
                af[0] = tf32u(as[mb * KPAD + ks + (lane & 3)]);
                af[1] = tf32u(as[(mb + 8) * KPAD + ks + (lane & 3)]);
                af[2] = tf32u(as[mb * KPAD + ks + (lane & 3) + 4]);
                af[3] = tf32u(as[(mb + 8) * KPAD + ks + (lane & 3) + 4]);
#pragma unroll
                for (int nt = 0; nt < 8; nt++) mma8(acc[mt][nt], af, bf[nt]);
            }
        }
        __syncthreads();
    }

    int lr = lane >> 2, lc2 = (lane & 3) * 2;
#pragma unroll
    for (int mt = 0; mt < 2; mt++) {
#pragma unroll
        for (int nt = 0; nt < 8; nt++) {
            int m = M0 + wm * 32 + mt * 16 + lr;
            int n = N0 + wn * 64 + nt * 8 + lc2;
            float b0 = has_bias ? bias[n] : 0.0f;
            float b1 = has_bias ? bias[n + 1] : 0.0f;
            float4 c = acc[mt][nt];
#pragma unroll
            for (int half = 0; half < 2; half++) {
                int mm = m + half * 8;
                float v0 = (half ? c.z : c.x) + b0;
                float v1 = (half ? c.w : c.y) + b1;
                if (mode == 0) {
                    *(float2*)(C + (size_t)mm * DM + n) = make_float2(v0, v1);
                } else if (mode == 1) {
                    int b = mm >> 10, s = mm & 1023;
                    int h = n >> 6, d = n & 63;
                    size_t idx = ((size_t)(b * HH + h) * TT + s) * DK + d;
                    *(float2*)(C + idx) = make_float2(v0, v1);
                } else if (mode == 2) {
                    int b = mm >> 10, s = mm & 1023;
                    int h = n >> 6, d = n & 63;
                    size_t idx = ((size_t)(b * HH + h) * DK + d) * TT + s;
                    C[idx] = v0;
                    C[idx + TT] = v1;
                } else { // mode 3
                    int h = n >> 6, d = n & 63;
                    size_t idx = ((size_t)h * TT + mm) * DK + d;
                    *(float2*)(C + idx) = make_float2(v0, v1);
                }
            }
        }
    }
}

// ======================================================================
// BD scatter: raw (m,n) -> shifted layout (scalar: alignment-hostile).
// ======================================================================
__device__ __forceinline__ void bd_scatter(float* out, int m, int n, float v)
{
    if (n >= TT - 1 - m) {
        out[(size_t)m * TT + (n - TT + 1 + m)] = v;
        if (m >= 1 && n == TT - 1 - m) out[(size_t)(m - 1) * TT + m] = 0.0f;
    } else if (m >= 1) {
        out[(size_t)(m - 1) * TT + (n + m + 1)] = v;
    }
}

// ======================================================================
// BD kernel — 256 threads, SINGLE-SHOT K=64 smem staging (1 barrier).
// ======================================================================
__global__ __launch_bounds__(256, 2) void bd_tc(const float* __restrict__ posb)
{
    extern __shared__ __align__(16) float dsm[];
    float* As = dsm;                 // 128 x KB
    float* Bs = dsm + 128 * KB;      // 128 x KB
    int bh = blockIdx.z;
    int b = bh >> 4, h = bh & 15;
    int tid = threadIdx.x;
    int M0 = blockIdx.y * 128, N0 = blockIdx.x * 128;
    int w = tid >> 5, lane = tid & 31;
    int wm = w & 3, wn = w >> 2;

    const float* Ab = g_qh + (size_t)b * TT * DM + h * DK;
    const float* Bb = g_p + (size_t)h * TT * DK;
    const float* pb = posb + h * DK;

    // load whole 128x64 A and B tiles (8 float4 per thread per tile)
    int r0 = tid >> 4;               // 0..15
    int c4 = (tid & 15) * 4;         // 0..60
    float4 pv = *(const float4*)(pb + c4);
#pragma unroll
    for (int i = 0; i < 8; i++) {
        int row = r0 + i * 16;
        float4 va = *(const float4*)(Ab + (size_t)(M0 + row) * DM + c4);
        float4 vb = *(const float4*)(Bb + (size_t)(N0 + row) * DK + c4);
        *(float4*)&As[row * KB + c4] = make_float4(
            to_tf32(va.x + pv.x), to_tf32(va.y + pv.y),
            to_tf32(va.z + pv.z), to_tf32(va.w + pv.w));
        *(float4*)&Bs[row * KB + c4] =
            make_float4(to_tf32(vb.x), to_tf32(vb.y), to_tf32(vb.z), to_tf32(vb.w));
    }
    __syncthreads();

    float4 acc[2][8];
#pragma unroll
    for (int i = 0; i < 2; i++)
#pragma unroll
        for (int j = 0; j < 8; j++) acc[i][j] = make_float4(0.f, 0.f, 0.f, 0.f);

#pragma unroll
    for (int ks = 0; ks < 64; ks += 8) {
        uint32_t bf[8][2];
#pragma unroll
        for (int nt = 0; nt < 8; nt++) {
            int nb = wn * 64 + nt * 8 + (lane >> 2);
            bf[nt][0] = __float_as_uint(Bs[nb * KB + ks + (lane & 3)]);
            bf[nt][1] = __float_as_uint(Bs[nb * KB + ks + (lane & 3) + 4]);
        }
#pragma unroll
        for (int mt = 0; mt < 2; mt++) {
            int mb = wm * 32 + mt * 16 + (lane >> 2);
            uint32_t af[4];
            af[0] = __float_as_uint(As[mb * KB + ks + (lane & 3)]);
            af[1] = __float_as_uint(As[(mb + 8) * KB + ks + (lane & 3)]);
            af[2] = __float_as_uint(As[mb * KB + ks + (lane & 3) + 4]);
            af[3] = __float_as_uint(As[(mb + 8) * KB + ks + (lane & 3) + 4]);
#pragma unroll
            for (int nt = 0; nt < 8; nt++) mma8(acc[mt][nt], af, bf[nt]);
        }
    }

    float* out = g_bd + (size_t)bh * TT * TT;
    int lr = lane >> 2, lc2 = (lane & 3) * 2;
#pragma unroll
    for (int mt = 0; mt < 2; mt++)
#pragma unroll
        for (int nt = 0; nt < 8; nt++) {
            int m = M0 + wm * 32 + mt * 16 + lr;
            int n = N0 + wn * 64 + nt * 8 + lc2;
            float4 c = acc[mt][nt];
            bd_scatter(out, m,     n,     c.x);
            bd_scatter(out, m,     n + 1, c.y);
            bd_scatter(out, m + 8, n,     c.z);
            bd_scatter(out, m + 8, n + 1, c.w);
        }
}

// ======================================================================
// Scores — 512 threads, SINGLE-SHOT K=64 staging (1 barrier in mainloop),
// wide shfl-regrouped epilogue + online softmax partials.
// ======================================================================
__global__ __launch_bounds__(512, 2) void scores_tc(
    const int* __restrict__ mask, float* __restrict__ outp,
    const float* __restrict__ posb)
{
    extern __shared__ __align__(16) float dsm[];
    float* As = dsm;
    float* Bs = dsm + 128 * KB;
    __shared__ float2 sred[128][4];
    int bh = blockIdx.z;
    int b = bh >> 4, h = bh & 15;
    int tid = threadIdx.x;
    int M0 = blockIdx.y * 128, N0 = blockIdx.x * 128;
    int w = tid >> 5, lane = tid & 31;
    int wm = w & 3, wn = w >> 2;
    int lr = lane >> 2, lc = lane & 3;

    const float* Ab = g_qh + (size_t)b * TT * DM + h * DK;
    const float* Bb = g_kh + (size_t)bh * TT * DK;
    const float* pb = posb + h * DK;

    // load whole 128x64 tiles (4 float4 per thread per tile)
    int r0 = tid >> 4;               // 0..31
    int c4 = (tid & 15) * 4;
    float4 pv = *(const float4*)(pb + c4);
#pragma unroll
    for (int i = 0; i < 4; i++) {
        int row = r0 + i * 32;
        float4 va = *(const float4*)(Ab + (size_t)(M0 + row) * DM + c4);
        float4 vb = *(const float4*)(Bb + (size_t)(N0 + row) * DK + c4);
        *(float4*)&As[row * KB + c4] = make_float4(
            to_tf32(va.x + pv.x), to_tf32(va.y + pv.y),
            to_tf32(va.z + pv.z), to_tf32(va.w + pv.w));
        *(float4*)&Bs[row * KB + c4] =
            make_float4(to_tf32(vb.x), to_tf32(vb.y), to_tf32(vb.z), to_tf32(vb.w));
    }
    __syncthreads();

    float4 acc[2][4];
#pragma unroll
    for (int i = 0; i < 2; i++)
#pragma unroll
        for (int j = 0; j < 4; j++) acc[i][j] = make_float4(0.f, 0.f, 0.f, 0.f);

#pragma unroll
    for (int ks = 0; ks < 64; ks += 8) {
        uint32_t bf[4][2];
#pragma unroll
        for (int nt = 0; nt < 4; nt++) {
            int nb = wn * 32 + nt * 8 + lr;
            bf[nt][0] = __float_as_uint(Bs[nb * KB + ks + lc]);
            bf[nt][1] = __float_as_uint(Bs[nb * KB + ks + lc + 4]);
        }
#pragma unroll
        for (int mt = 0; mt < 2; mt++) {
            int mb = wm * 32 + mt * 16 + lr;
            uint32_t af[4];
            af[0] = __float_as_uint(As[mb * KB + ks + lc]);
            af[1] = __float_as_uint(As[(mb + 8) * KB + ks + lc]);
            af[2] = __float_as_uint(As[mb * KB + ks + lc + 4]);
            af[3] = __float_as_uint(As[(mb + 8) * KB + ks + lc + 4]);
#pragma unroll
            for (int nt = 0; nt < 4; nt++) mma8(acc[mt][nt], af, bf[nt]);
        }
    }

    const float* BD = g_bd + (size_t)bh * TT * TT;
    const int* mk = mask + (size_t)b * TT * TT;
    float* out = outp + (size_t)bh * TT * TT;

    // shfl-regrouped epilogue
    int rowoff = (lc & 1) * 8;
    int colgrp = (lc & 2) * 2;
#pragma unroll
    for (int mt = 0; mt < 2; mt++) {
        int rbase = wm * 32 + mt * 16 + lr;
        int a = M0 + rbase + rowoff;
        float4 sv[4];
        float mloc = -1e30f;
#pragma unroll
        for (int nt = 0; nt < 4; nt++) {
            int n = N0 + wn * 32 + nt * 8 + colgrp;
            float4 c = acc[mt][nt];
            float px = __shfl_xor_sync(0xffffffffu, c.x, 1);
            float py = __shfl_xor_sync(0xffffffffu, c.y, 1);
            float pz = __shfl_xor_sync(0xffffffffu, c.z, 1);
            float pw = __shfl_xor_sync(0xffffffffu, c.w, 1);
            float4 v = (lc & 1) ? make_float4(pz, pw, c.z, c.w)
                                : make_float4(c.x, c.y, px, py);
            float4 bd4 = *(const float4*)(BD + (size_t)a * TT + n);
            int4 mv = *(const int4*)(mk + (size_t)a * TT + n);
            float4 s;
            s.x = (v.x + bd4.x) * 0.125f; if (mv.x == 0) s.x = -10000.0f;
            s.y = (v.y + bd4.y) * 0.125f; if (mv.y == 0) s.y = -10000.0f;
            s.z = (v.z + bd4.z) * 0.125f; if (mv.z == 0) s.z = -10000.0f;
            s.w = (v.w + bd4.w) * 0.125f; if (mv.w == 0) s.w = -10000.0f;
            __stcs((float4*)(out + (size_t)a * TT + n), s);
            sv[nt] = s;
            mloc = fmaxf(mloc, fmaxf(fmaxf(s.x, s.y), fmaxf(s.z, s.w)));
        }
        float ssum = 0.0f;
#pragma unroll
        for (int nt = 0; nt < 4; nt++) {
            ssum += __expf(sv[nt].x - mloc) + __expf(sv[nt].y - mloc)
                  + __expf(sv[nt].z - mloc) + __expf(sv[nt].w - mloc);
        }
        float mo = __shfl_xor_sync(0xffffffffu, mloc, 2);
        float so = __shfl_xor_sync(0xffffffffu, ssum, 2);
        float M2 = fmaxf(mloc, mo);
        ssum = ssum * __expf(mloc - M2) + so * __expf(mo - M2);
        mloc = M2;
        if (lc < 2) sred[rbase + lc * 8][wn] = make_float2(mloc, ssum);
    }
    __syncthreads();
    if (tid < 128) {
        float2 q = sred[tid][0];
        float M = q.x, S = q.y;
#pragma unroll
        for (int j = 1; j < 4; j++) {
            float2 qq = sred[tid][j];
            float M2 = fmaxf(M, qq.x);
            S = S * __expf(M - M2) + qq.y * __expf(qq.x - M2);
            M = M2;
        }
        g_part[((size_t)bh * TT + M0 + tid) * 8 + (N0 >> 7)] = make_float2(M, S);
    }
}

// ======================================================================
// Combine per-tile partials -> per-row (max, 1/sum)
// ======================================================================
__global__ __launch_bounds__(256) void combine_stats()
{
    int idx = blockIdx.x * 256 + threadIdx.x;
    const float2* p = g_part + (size_t)idx * 8;
    float2 q = p[0];
    float M = q.x, S = q.y;
#pragma unroll
    for (int j = 1; j < 8; j++) {
        float2 qq = p[j];
        float M2 = fmaxf(M, qq.x);
        S = S * __expf(M - M2) + qq.y * __expf(qq.x - M2);
        M = M2;
    }
    g_ms[idx] = make_float2(M, 1.0f / S);
}

// ======================================================================
// PV fused — R8 256-thread version (measured best).
// ======================================================================
__global__ __launch_bounds__(256, 2) void pv_fused(
    float* __restrict__ attn, float* __restrict__ concat)
{
    __shared__ __align__(16) float As[128 * KPAD];
    __shared__ __align__(16) float Bs[2 * 64 * KPAD];
    int bh = blockIdx.z;
    int b = bh >> 4, h = bh & 15;
    int tid = threadIdx.x;
    int M0 = blockIdx.y * 128;
    int w = tid >> 5, lane = tid & 31;
    int wm = w & 3, wn = w >> 2;
    int r = tid >> 2, c4 = (tid & 3) * 4;

    float* Ag = attn + (size_t)bh * TT * TT + (size_t)(M0 + r) * TT + c4;
    const float* Bg = g_vt + (size_t)bh * DK * TT + (size_t)r * TT + c4;
    uint32_t sB = (uint32_t)__cvta_generic_to_shared(Bs);
    uint32_t offB = (r * KPAD + c4) * 4;

    float2 ms0 = g_ms[(size_t)bh * TT + M0 + r];
    float2 ms1 = g_ms[(size_t)bh * TT + M0 + r + 64];

    float4 acc[2][4];
#pragma unroll
    for (int i = 0; i < 2; i++)
#pragma unroll
        for (int j = 0; j < 4; j++) acc[i][j] = make_float4(0.f, 0.f, 0.f, 0.f);

    float4 ra0 = *(const float4*)(Ag);
    float4 ra1 = *(const float4*)(Ag + (size_t)64 * TT);
    cpa16(sB + offB, Bg);
    cp_commit();

    const int KT = TT >> 4;
    for (int kt = 0; kt < KT; kt++) {
        int k0 = kt << 4;
        float4 p0, p1;
        p0.x = __expf(ra0.x - ms0.x) * ms0.y;
        p0.y = __expf(ra0.y - ms0.x) * ms0.y;
        p0.z = __expf(ra0.z - ms0.x) * ms0.y;
        p0.w = __expf(ra0.w - ms0.x) * ms0.y;
        p1.x = __expf(ra1.x - ms1.x) * ms1.y;
        p1.y = __expf(ra1.y - ms1.x) * ms1.y;
        p1.z = __expf(ra1.z - ms1.x) * ms1.y;
        p1.w = __expf(ra1.w - ms1.x) * ms1.y;
        __stcs((float4*)(Ag + k0), p0);
        __stcs((float4*)(Ag + (size_t)64 * TT + k0), p1);
        *(float4*)&As[r * KPAD + c4] =
            make_float4(to_tf32(p0.x), to_tf32(p0.y), to_tf32(p0.z), to_tf32(p0.w));
        *(float4*)&As[(r + 64) * KPAD + c4] =
            make_float4(to_tf32(p1.x), to_tf32(p1.y), to_tf32(p1.z), to_tf32(p1.w));

        if (kt + 1 < KT) {
            int k0n = (kt + 1) << 4;
            ra0 = *(const float4*)(Ag + k0n);
            ra1 = *(const float4*)(Ag + (size_t)64 * TT + k0n);
            cpa16(sB + ((kt + 1) & 1) * 64 * KPAD * 4 + offB, Bg + k0n);
            cp_commit();
            cp_wait<1>();
        } else {
            cp_wait<0>();
        }
        __syncthreads();

        const float* bs = Bs + (kt & 1) * 64 * KPAD;
#pragma unroll
        for (int ks = 0; ks < 16; ks += 8) {
            uint32_t bf[4][2];
#pragma unroll
            for (int nt = 0; nt < 4; nt++) {
                int nb = wn * 32 + nt * 8 + (lane >> 2);
                bf[nt][0] = tf32u(bs[nb * KPAD + ks + (lane & 3)]);
                bf[nt][1] = tf32u(bs[nb * KPAD + ks + (lane & 3) + 4]);
            }
#pragma unroll
            for (int mt = 0; mt < 2; mt++) {
                int mb = wm * 32 + mt * 16 + (lane >> 2);
                uint32_t af[4];
                af[0] = __float_as_uint(As[mb * KPAD + ks + (lane & 3)]);
                af[1] = __float_as_uint(As[(mb + 8) * KPAD + ks + (lane & 3)]);
                af[2] = __float_as_uint(As[mb * KPAD + ks + (lane & 3) + 4]);
                af[3] = __float_as_uint(As[(mb + 8) * KPAD + ks + (lane & 3) + 4]);
#pragma unroll
                for (int nt = 0; nt < 4; nt++) mma8(acc[mt][nt], af, bf[nt]);
            }
        }
        __syncthreads();
    }

    int lr = lane >> 2, lc2 = (lane & 3) * 2;
#pragma unroll
    for (int mt = 0; mt < 2; mt++)
#pragma unroll
        for (int nt = 0; nt < 4; nt++) {
            int t = M0 + wm * 32 + mt * 16 + lr;
            int d = wn * 32 + nt * 8 + lc2;
            float4 c = acc[mt][nt];
            *(float2*)(concat + ((size_t)(b * TT + t)) * DM + h * DK + d) =
                make_float2(c.x, c.y);
            *(float2*)(concat + ((size_t)(b * TT + t + 8)) * DM + h * DK + d) =
                make_float2(c.z, c.w);
        }
}

// ======================================================================
extern "C" void kernel_launch(void* const* d_in, const int* in_sizes, int n_in,
                              void* d_out, int out_size)
{
    const float* q    = (const float*)d_in[0];
    const float* k    = (const float*)d_in[1];
    const float* v    = (const float*)d_in[2];
    const float* pos  = (const float*)d_in[3];
    const int*   mask = (const int*)d_in[4];
    const float* Wq   = (const float*)d_in[5];
    const float* bq   = (const float*)d_in[6];
    const float* Wk   = (const float*)d_in[7];
    const float* bk   = (const float*)d_in[8];
    const float* Wv   = (const float*)d_in[9];
    const float* bv   = (const float*)d_in[10];
    const float* Wp   = (const float*)d_in[11];
    const float* pbu  = (const float*)d_in[12];
    const float* pbv  = (const float*)d_in[13];
    const float* Wo   = (const float*)d_in[14];
    const float* bo   = (const float*)d_in[15];

    float *qh, *kh, *vt, *pp, *cc;
    cudaGetSymbolAddress((void**)&qh, g_qh);
    cudaGetSymbolAddress((void**)&kh, g_kh);
    cudaGetSymbolAddress((void**)&vt, g_vt);
    cudaGetSymbolAddress((void**)&pp, g_p);
    cudaGetSymbolAddress((void**)&cc, g_concat);

    float* out  = (float*)d_out;
    float* attn = out + (size_t)BSZ * TT * DM;

    static bool attr_done = false;
    if (!attr_done) {
        cudaFuncSetAttribute(bd_tc, cudaFuncAttributeMaxDynamicSharedMemorySize, QK_SMEM);
        cudaFuncSetAttribute(scores_tc, cudaFuncAttributeMaxDynamicSharedMemorySize, QK_SMEM);
        attr_done = true;
    }

    dim3 blk512(512);
    dim3 blk256(256);

    // Q, K, V projections batched (z -> mode 0/1/2)
    QKVArgs qa;
    qa.A[0] = q;  qa.A[1] = k;  qa.A[2] = v;
    qa.B[0] = Wq; qa.B[1] = Wk; qa.B[2] = Wv;
    qa.bias[0] = bq; qa.bias[1] = bk; qa.bias[2] = bv;
    qa.C[0] = qh; qa.C[1] = kh; qa.C[2] = vt;
    gemm_pipe<<<dim3(8, 32, 3), blk256>>>(qa, DM, -1);

    // pos projection (mode 3)
    QKVArgs pa = {};
    pa.A[0] = pos; pa.B[0] = Wp; pa.bias[0] = nullptr; pa.C[0] = pp;
    gemm_pipe<<<dim3(8, 8, 1), blk256>>>(pa, DM, 3);

    // BD = (qh + pos_bias_v) @ p^T, written SHIFTED into g_bd
    bd_tc<<<dim3(8, 8, 64), blk256, QK_SMEM>>>(pbv);

    // raw scores + per-tile softmax partials
    scores_tc<<<dim3(8, 8, 64), blk512, QK_SMEM>>>(mask, attn, pbu);

    // combine partials -> per-row (max, 1/sum)
    combine_stats<<<dim3(BSZ * HH * TT / 256), blk256>>>();

    // normalize in place + PV -> concat
    pv_fused<<<dim3(1, 8, 64), blk256>>>(attn, cc);

    // output = concat @ Wo^T + bo (mode 0)
    QKVArgs oa = {};
    oa.A[0] = cc; oa.B[0] = Wo; oa.bias[0] = bo; oa.C[0] = out;
    gemm_pipe<<<dim3(8, 32, 1), blk256>>>(oa, DM, 0);
}

// round 15
// speedup vs baseline: 1.0026x; 1.0026x over previous
#include <cuda_runtime.h>
#include <cstdint>

#define BSZ 4
#define TT  1024
#define DM  1024
#define HH  16
#define DK  64
#define KPAD 20
#define STG (128 * KPAD)
#define KB 68
#define QK_SMEM (2 * 128 * KB * 4)

// ---- device scratch (alloc-free rule: __device__ globals) ----
__device__ float g_qh[BSZ * TT * DM];              // (b, t, h, d)
__device__ float g_kh[BSZ * TT * DM];              // (b, h, t, d)
__device__ float g_vt[BSZ * TT * DM];              // (b, h, d, t)
__device__ float g_p[TT * DM];                     // (h, t, d)
__device__ float g_bd[67108864];                   // SHIFTED bd (b,h,t,s)
__device__ float g_concat[BSZ * TT * DM];          // (b, t, h*d)
__device__ float2 g_part[BSZ * HH * TT * 8];       // per-(row, colTile) (max, sumexp)
__device__ float2 g_ms[BSZ * HH * TT];             // per-row (max, 1/sum)

// ---------------------------------------------------------------
__device__ __forceinline__ float to_tf32(float x) {
    uint32_t u;
    asm("cvt.rna.tf32.f32 %0, %1;" : "=r"(u) : "f"(x));
    return __uint_as_float(u);
}
__device__ __forceinline__ uint32_t tf32u(float x) {
    uint32_t u;
    asm("cvt.rna.tf32.f32 %0, %1;" : "=r"(u) : "f"(x));
    return u;
}

__device__ __forceinline__ void mma8(float4& d, const uint32_t a[4], const uint32_t b[2]) {
    asm volatile(
        "mma.sync.aligned.m16n8k8.row.col.f32.tf32.tf32.f32 "
        "{%0,%1,%2,%3}, {%4,%5,%6,%7}, {%8,%9}, {%0,%1,%2,%3};\n"
        : "+f"(d.x), "+f"(d.y), "+f"(d.z), "+f"(d.w)
        : "r"(a[0]), "r"(a[1]), "r"(a[2]), "r"(a[3]), "r"(b[0]), "r"(b[1]));
}

__device__ __forceinline__ void cpa16(uint32_t saddr, const float* g) {
    asm volatile("cp.async.ca.shared.global [%0], [%1], 16;\n" :: "r"(saddr), "l"(g));
}
__device__ __forceinline__ void cp_commit() {
    asm volatile("cp.async.commit_group;\n");
}
template <int N>
__device__ __forceinline__ void cp_wait() {
    asm volatile("cp.async.wait_group %0;\n" :: "n"(N));
}

struct QKVArgs {
    const float* A[3];
    const float* B[3];
    const float* bias[3];
    float* C[3];
};

// ======================================================================
// Pipelined tensor-core NT GEMM — 256-thread (best measured)
// ======================================================================
__global__ __launch_bounds__(256, 2) void gemm_pipe(QKVArgs args, int K, int mode_sel)
{
    __shared__ __align__(16) float As[2 * STG];
    __shared__ __align__(16) float Bs[2 * STG];
    int z = blockIdx.z;
    int mode = (mode_sel >= 0) ? mode_sel : z;
    const float* A = args.A[z];
    const float* B = args.B[z];
    const float* bias = args.bias[z];
    float* C = args.C[z];
    bool has_bias = (bias != nullptr);

    int tid = threadIdx.x;
    int M0 = blockIdx.y * 128, N0 = blockIdx.x * 128;
    int w = tid >> 5, lane = tid & 31;
    int wm = w & 3, wn = w >> 2;
    int r = tid >> 2, c4 = (tid & 3) * 4;

    float4 acc[2][8];
#pragma unroll
    for (int i = 0; i < 2; i++)
#pragma unroll
        for (int j = 0; j < 8; j++) acc[i][j] = make_float4(0.f, 0.f, 0.f, 0.f);

    const float* Ag = A + (size_t)(M0 + r) * K + c4;
    const float* Bg = B + (size_t)(N0 + r) * K + c4;
    uint32_t sA = (uint32_t)__cvta_generic_to_shared(As);
    uint32_t sB = (uint32_t)__cvta_generic_to_shared(Bs);
    uint32_t offA0 = (r * KPAD + c4) * 4;
    uint32_t offA1 = ((r + 64) * KPAD + c4) * 4;

    cpa16(sA + offA0, Ag);
    cpa16(sA + offA1, Ag + (size_t)64 * K);
    cpa16(sB + offA0, Bg);
    cpa16(sB + offA1, Bg + (size_t)64 * K);
    cp_commit();

    int KT = K >> 4;
    for (int kt = 0; kt < KT; kt++) {
        if (kt + 1 < KT) {
            int st = (kt + 1) & 1;
            int k0 = (kt + 1) << 4;
            cpa16(sA + st * STG * 4 + offA0, Ag + k0);
            cpa16(sA + st * STG * 4 + offA1, Ag + (size_t)64 * K + k0);
            cpa16(sB + st * STG * 4 + offA0, Bg + k0);
            cpa16(sB + st * STG * 4 + offA1, Bg + (size_t)64 * K + k0);
            cp_commit();
            cp_wait<1>();
        } else {
            cp_wait<0>();
        }
        __syncthreads();
        const float* as = As + (kt & 1) * STG;
        const float* bs = Bs + (kt & 1) * STG;
#pragma unroll
        for (int ks = 0; ks < 16; ks += 8) {
            uint32_t bf[8][2];
#pragma unroll
            for (int nt = 0; nt < 8; nt++) {
                int nb = wn * 64 + nt * 8 + (lane >> 2);
                bf[nt][0] = tf32u(bs[nb * KPAD + ks + (lane & 3)]);
                bf[nt][1] = tf32u(bs[nb * KPAD + ks + (lane & 3) + 4]);
            }
#pragma unroll
            for (int mt = 0; mt < 2; mt++) {
                int mb = wm * 32 + mt * 16 + (lane >> 2);
                uint32_t af[4];
                af[0] = tf32u(as[mb * KPAD + ks + (lane & 3)]);
                af[1] = tf32u(as[(mb + 8) * KPAD + ks + (lane & 3)]);
                af[2] = tf32u(as[mb * KPAD + ks + (lane & 3) + 4]);
                af[3] = tf32u(as[(mb + 8) * KPAD + ks + (lane & 3) + 4]);
#pragma unroll
                for (int nt = 0; nt < 8; nt++) mma8(acc[mt][nt], af, bf[nt]);
            }
        }
        __syncthreads();
    }

    int lr = lane >> 2, lc2 = (lane & 3) * 2;
#pragma unroll
    for (int mt = 0; mt < 2; mt++) {
#pragma unroll
        for (int nt = 0; nt < 8; nt++) {
            int m = M0 + wm * 32 + mt * 16 + lr;
            int n = N0 + wn * 64 + nt * 8 + lc2;
            float b0 = has_bias ? bias[n] : 0.0f;
            float b1 = has_bias ? bias[n + 1] : 0.0f;
            float4 c = acc[mt][nt];
#pragma unroll
            for (int half = 0; half < 2; half++) {
                int mm = m + half * 8;
                float v0 = (half ? c.z : c.x) + b0;
                float v1 = (half ? c.w : c.y) + b1;
                if (mode == 0) {
                    *(float2*)(C + (size_t)mm * DM + n) = make_float2(v0, v1);
                } else if (mode == 1) {
                    int b = mm >> 10, s = mm & 1023;
                    int h = n >> 6, d = n & 63;
                    size_t idx = ((size_t)(b * HH + h) * TT + s) * DK + d;
                    *(float2*)(C + idx) = make_float2(v0, v1);
                } else if (mode == 2) {
                    int b = mm >> 10, s = mm & 1023;
                    int h = n >> 6, d = n & 63;
                    size_t idx = ((size_t)(b * HH + h) * DK + d) * TT + s;
                    C[idx] = v0;
                    C[idx + TT] = v1;
                } else { // mode 3
                    int h = n >> 6, d = n & 63;
                    size_t idx = ((size_t)h * TT + mm) * DK + d;
                    *(float2*)(C + idx) = make_float2(v0, v1);
                }
            }
        }
    }
}

// ======================================================================
// BD scatter: raw (m,n) -> shifted layout (scalar: alignment-hostile).
// ======================================================================
__device__ __forceinline__ void bd_scatter(float* out, int m, int n, float v)
{
    if (n >= TT - 1 - m) {
        out[(size_t)m * TT + (n - TT + 1 + m)] = v;
        if (m >= 1 && n == TT - 1 - m) out[(size_t)(m - 1) * TT + m] = 0.0f;
    } else if (m >= 1) {
        out[(size_t)(m - 1) * TT + (n + m + 1)] = v;
    }
}

// ======================================================================
// BD kernel — 256 threads, SINGLE-SHOT K=64 smem staging (1 barrier).
// ======================================================================
__global__ __launch_bounds__(256, 2) void bd_tc(const float* __restrict__ posb)
{
    extern __shared__ __align__(16) float dsm[];
    float* As = dsm;                 // 128 x KB
    float* Bs = dsm + 128 * KB;      // 128 x KB
    int bh = blockIdx.z;
    int b = bh >> 4, h = bh & 15;
    int tid = threadIdx.x;
    int M0 = blockIdx.y * 128, N0 = blockIdx.x * 128;
    int w = tid >> 5, lane = tid & 31;
    int wm = w & 3, wn = w >> 2;

    const float* Ab = g_qh + (size_t)b * TT * DM + h * DK;
    const float* Bb = g_p + (size_t)h * TT * DK;
    const float* pb = posb + h * DK;

    // load whole 128x64 A and B tiles (8 float4 per thread per tile)
    int r0 = tid >> 4;               // 0..15
    int c4 = (tid & 15) * 4;         // 0..60
    float4 pv = *(const float4*)(pb + c4);
#pragma unroll
    for (int i = 0; i < 8; i++) {
        int row = r0 + i * 16;
        float4 va = *(const float4*)(Ab + (size_t)(M0 + row) * DM + c4);
        float4 vb = *(const float4*)(Bb + (size_t)(N0 + row) * DK + c4);
        *(float4*)&As[row * KB + c4] = make_float4(
            to_tf32(va.x + pv.x), to_tf32(va.y + pv.y),
            to_tf32(va.z + pv.z), to_tf32(va.w + pv.w));
        *(float4*)&Bs[row * KB + c4] =
            make_float4(to_tf32(vb.x), to_tf32(vb.y), to_tf32(vb.z), to_tf32(vb.w));
    }
    __syncthreads();

    float4 acc[2][8];
#pragma unroll
    for (int i = 0; i < 2; i++)
#pragma unroll
        for (int j = 0; j < 8; j++) acc[i][j] = make_float4(0.f, 0.f, 0.f, 0.f);

#pragma unroll
    for (int ks = 0; ks < 64; ks += 8) {
        uint32_t bf[8][2];
#pragma unroll
        for (int nt = 0; nt < 8; nt++) {
            int nb = wn * 64 + nt * 8 + (lane >> 2);
            bf[nt][0] = __float_as_uint(Bs[nb * KB + ks + (lane & 3)]);
            bf[nt][1] = __float_as_uint(Bs[nb * KB + ks + (lane & 3) + 4]);
        }
#pragma unroll
        for (int mt = 0; mt < 2; mt++) {
            int mb = wm * 32 + mt * 16 + (lane >> 2);
            uint32_t af[4];
            af[0] = __float_as_uint(As[mb * KB + ks + (lane & 3)]);
            af[1] = __float_as_uint(As[(mb + 8) * KB + ks + (lane & 3)]);
            af[2] = __float_as_uint(As[mb * KB + ks + (lane & 3) + 4]);
            af[3] = __float_as_uint(As[(mb + 8) * KB + ks + (lane & 3) + 4]);
#pragma unroll
            for (int nt = 0; nt < 8; nt++) mma8(acc[mt][nt], af, bf[nt]);
        }
    }

    float* out = g_bd + (size_t)bh * TT * TT;
    int lr = lane >> 2, lc2 = (lane & 3) * 2;
#pragma unroll
    for (int mt = 0; mt < 2; mt++)
#pragma unroll
        for (int nt = 0; nt < 8; nt++) {
            int m = M0 + wm * 32 + mt * 16 + lr;
            int n = N0 + wn * 64 + nt * 8 + lc2;
            float4 c = acc[mt][nt];
            bd_scatter(out, m,     n,     c.x);
            bd_scatter(out, m,     n + 1, c.y);
            bd_scatter(out, m + 8, n,     c.z);
            bd_scatter(out, m + 8, n + 1, c.w);
        }
}

// ======================================================================
// Scores — 512 threads, SINGLE-SHOT K=64 staging (1 barrier in mainloop),
// wide shfl-regrouped epilogue + online softmax partials.
// ======================================================================
__global__ __launch_bounds__(512, 2) void scores_tc(
    const int* __restrict__ mask, float* __restrict__ outp,
    const float* __restrict__ posb)
{
    extern __shared__ __align__(16) float dsm[];
    float* As = dsm;
    float* Bs = dsm + 128 * KB;
    __shared__ float2 sred[128][4];
    int bh = blockIdx.z;
    int b = bh >> 4, h = bh & 15;
    int tid = threadIdx.x;
    int M0 = blockIdx.y * 128, N0 = blockIdx.x * 128;
    int w = tid >> 5, lane = tid & 31;
    int wm = w & 3, wn = w >> 2;
    int lr = lane >> 2, lc = lane & 3;

    const float* Ab = g_qh + (size_t)b * TT * DM + h * DK;
    const float* Bb = g_kh + (size_t)bh * TT * DK;
    const float* pb = posb + h * DK;

    // load whole 128x64 tiles (4 float4 per thread per tile)
    int r0 = tid >> 4;               // 0..31
    int c4 = (tid & 15) * 4;
    float4 pv = *(const float4*)(pb + c4);
#pragma unroll
    for (int i = 0; i < 4; i++) {
        int row = r0 + i * 32;
        float4 va = *(const float4*)(Ab + (size_t)(M0 + row) * DM + c4);
        float4 vb = *(const float4*)(Bb + (size_t)(N0 + row) * DK + c4);
        *(float4*)&As[row * KB + c4] = make_float4(
            to_tf32(va.x + pv.x), to_tf32(va.y + pv.y),
            to_tf32(va.z + pv.z), to_tf32(va.w + pv.w));
        *(float4*)&Bs[row * KB + c4] =
            make_float4(to_tf32(vb.x), to_tf32(vb.y), to_tf32(vb.z), to_tf32(vb.w));
    }
    __syncthreads();

    float4 acc[2][4];
#pragma unroll
    for (int i = 0; i < 2; i++)
#pragma unroll
        for (int j = 0; j < 4; j++) acc[i][j] = make_float4(0.f, 0.f, 0.f, 0.f);

#pragma unroll
    for (int ks = 0; ks < 64; ks += 8) {
        uint32_t bf[4][2];
#pragma unroll
        for (int nt = 0; nt < 4; nt++) {
            int nb = wn * 32 + nt * 8 + lr;
            bf[nt][0] = __float_as_uint(Bs[nb * KB + ks + lc]);
            bf[nt][1] = __float_as_uint(Bs[nb * KB + ks + lc + 4]);
        }
#pragma unroll
        for (int mt = 0; mt < 2; mt++) {
            int mb = wm * 32 + mt * 16 + lr;
            uint32_t af[4];
            af[0] = __float_as_uint(As[mb * KB + ks + lc]);
            af[1] = __float_as_uint(As[(mb + 8) * KB + ks + lc]);
            af[2] = __float_as_uint(As[mb * KB + ks + lc + 4]);
            af[3] = __float_as_uint(As[(mb + 8) * KB + ks + lc + 4]);
#pragma unroll
            for (int nt = 0; nt < 4; nt++) mma8(acc[mt][nt], af, bf[nt]);
        }
    }

    const float* BD = g_bd + (size_t)bh * TT * TT;
    const int* mk = mask + (size_t)b * TT * TT;
    float* out = outp + (size_t)bh * TT * TT;

    // shfl-regrouped epilogue
    int rowoff = (lc & 1) * 8;
    int colgrp = (lc & 2) * 2;
#pragma unroll
    for (int mt = 0; mt < 2; mt++) {
        int rbase = wm * 32 + mt * 16 + lr;
        int a = M0 + rbase + rowoff;
        float4 sv[4];
        float mloc = -1e30f;
#pragma unroll
        for (int nt = 0; nt < 4; nt++) {
            int n = N0 + wn * 32 + nt * 8 + colgrp;
            float4 c = acc[mt][nt];
            float px = __shfl_xor_sync(0xffffffffu, c.x, 1);
            float py = __shfl_xor_sync(0xffffffffu, c.y, 1);
            float pz = __shfl_xor_sync(0xffffffffu, c.z, 1);
            float pw = __shfl_xor_sync(0xffffffffu, c.w, 1);
            float4 v = (lc & 1) ? make_float4(pz, pw, c.z, c.w)
                                : make_float4(c.x, c.y, px, py);
            float4 bd4 = *(const float4*)(BD + (size_t)a * TT + n);
            int4 mv = *(const int4*)(mk + (size_t)a * TT + n);
            float4 s;
            s.x = (v.x + bd4.x) * 0.125f; if (mv.x == 0) s.x = -10000.0f;
            s.y = (v.y + bd4.y) * 0.125f; if (mv.y == 0) s.y = -10000.0f;
            s.z = (v.z + bd4.z) * 0.125f; if (mv.z == 0) s.z = -10000.0f;
            s.w = (v.w + bd4.w) * 0.125f; if (mv.w == 0) s.w = -10000.0f;
            __stcs((float4*)(out + (size_t)a * TT + n), s);
            sv[nt] = s;
            mloc = fmaxf(mloc, fmaxf(fmaxf(s.x, s.y), fmaxf(s.z, s.w)));
        }
        float ssum = 0.0f;
#pragma unroll
        for (int nt = 0; nt < 4; nt++) {
            ssum += __expf(sv[nt].x - mloc) + __expf(sv[nt].y - mloc)
                  + __expf(sv[nt].z - mloc) + __expf(sv[nt].w - mloc);
        }
        float mo = __shfl_xor_sync(0xffffffffu, mloc, 2);
        float so = __shfl_xor_sync(0xffffffffu, ssum, 2);
        float M2 = fmaxf(mloc, mo);
        ssum = ssum * __expf(mloc - M2) + so * __expf(mo - M2);
        mloc = M2;
        if (lc < 2) sred[rbase + lc * 8][wn] = make_float2(mloc, ssum);
    }
    __syncthreads();
    if (tid < 128) {
        float2 q = sred[tid][0];
        float M = q.x, S = q.y;
#pragma unroll
        for (int j = 1; j < 4; j++) {
            float2 qq = sred[tid][j];
            float M2 = fmaxf(M, qq.x);
            S = S * __expf(M - M2) + qq.y * __expf(qq.x - M2);
            M = M2;
        }
        g_part[((size_t)bh * TT + M0 + tid) * 8 + (N0 >> 7)] = make_float2(M, S);
    }
}

// ======================================================================
// Combine per-tile partials -> per-row (max, 1/sum)
// ======================================================================
__global__ __launch_bounds__(256) void combine_stats()
{
    int idx = blockIdx.x * 256 + threadIdx.x;
    const float2* p = g_part + (size_t)idx * 8;
    float2 q = p[0];
    float M = q.x, S = q.y;
#pragma unroll
    for (int j = 1; j < 8; j++) {
        float2 qq = p[j];
        float M2 = fmaxf(M, qq.x);
        S = S * __expf(M - M2) + qq.y * __expf(qq.x - M2);
        M = M2;
    }
    g_ms[idx] = make_float2(M, 1.0f / S);
}

// ======================================================================
// PV fused — R8 256-thread version (measured best).
// ======================================================================
__global__ __launch_bounds__(256, 2) void pv_fused(
    float* __restrict__ attn, float* __restrict__ concat)
{
    __shared__ __align__(16) float As[128 * KPAD];
    __shared__ __align__(16) float Bs[2 * 64 * KPAD];
    int bh = blockIdx.z;
    int b = bh >> 4, h = bh & 15;
    int tid = threadIdx.x;
    int M0 = blockIdx.y * 128;
    int w = tid >> 5, lane = tid & 31;
    int wm = w & 3, wn = w >> 2;
    int r = tid >> 2, c4 = (tid & 3) * 4;

    float* Ag = attn + (size_t)bh * TT * TT + (size_t)(M0 + r) * TT + c4;
    const float* Bg = g_vt + (size_t)bh * DK * TT + (size_t)r * TT + c4;
    uint32_t sB = (uint32_t)__cvta_generic_to_shared(Bs);
    uint32_t offB = (r * KPAD + c4) * 4;

    float2 ms0 = g_ms[(size_t)bh * TT + M0 + r];
    float2 ms1 = g_ms[(size_t)bh * TT + M0 + r + 64];

    float4 acc[2][4];
#pragma unroll
    for (int i = 0; i < 2; i++)
#pragma unroll
        for (int j = 0; j < 4; j++) acc[i][j] = make_float4(0.f, 0.f, 0.f, 0.f);

    float4 ra0 = *(const float4*)(Ag);
    float4 ra1 = *(const float4*)(Ag + (size_t)64 * TT);
    cpa16(sB + offB, Bg);
    cp_commit();

    const int KT = TT >> 4;
    for (int kt = 0; kt < KT; kt++) {
        int k0 = kt << 4;
        float4 p0, p1;
        p0.x = __expf(ra0.x - ms0.x) * ms0.y;
        p0.y = __expf(ra0.y - ms0.x) * ms0.y;
        p0.z = __expf(ra0.z - ms0.x) * ms0.y;
        p0.w = __expf(ra0.w - ms0.x) * ms0.y;
        p1.x = __expf(ra1.x - ms1.x) * ms1.y;
        p1.y = __expf(ra1.y - ms1.x) * ms1.y;
        p1.z = __expf(ra1.z - ms1.x) * ms1.y;
        p1.w = __expf(ra1.w - ms1.x) * ms1.y;
        __stcs((float4*)(Ag + k0), p0);
        __stcs((float4*)(Ag + (size_t)64 * TT + k0), p1);
        *(float4*)&As[r * KPAD + c4] =
            make_float4(to_tf32(p0.x), to_tf32(p0.y), to_tf32(p0.z), to_tf32(p0.w));
        *(float4*)&As[(r + 64) * KPAD + c4] =
            make_float4(to_tf32(p1.x), to_tf32(p1.y), to_tf32(p1.z), to_tf32(p1.w));

        if (kt + 1 < KT) {
            int k0n = (kt + 1) << 4;
            ra0 = *(const float4*)(Ag + k0n);
            ra1 = *(const float4*)(Ag + (size_t)64 * TT + k0n);
            cpa16(sB + ((kt + 1) & 1) * 64 * KPAD * 4 + offB, Bg + k0n);
            cp_commit();
            cp_wait<1>();
        } else {
            cp_wait<0>();
        }
        __syncthreads();

        const float* bs = Bs + (kt & 1) * 64 * KPAD;
#pragma unroll
        for (int ks = 0; ks < 16; ks += 8) {
            uint32_t bf[4][2];
#pragma unroll
            for (int nt = 0; nt < 4; nt++) {
                int nb = wn * 32 + nt * 8 + (lane >> 2);
                bf[nt][0] = tf32u(bs[nb * KPAD + ks + (lane & 3)]);
                bf[nt][1] = tf32u(bs[nb * KPAD + ks + (lane & 3) + 4]);
            }
#pragma unroll
            for (int mt = 0; mt < 2; mt++) {
                int mb = wm * 32 + mt * 16 + (lane >> 2);
                uint32_t af[4];
                af[0] = __float_as_uint(As[mb * KPAD + ks + (lane & 3)]);
                af[1] = __float_as_uint(As[(mb + 8) * KPAD + ks + (lane & 3)]);
                af[2] = __float_as_uint(As[mb * KPAD + ks + (lane & 3) + 4]);
                af[3] = __float_as_uint(As[(mb + 8) * KPAD + ks + (lane & 3) + 4]);
#pragma unroll
                for (int nt = 0; nt < 4; nt++) mma8(acc[mt][nt], af, bf[nt]);
            }
        }
        __syncthreads();
    }

    int lr = lane >> 2, lc2 = (lane & 3) * 2;
#pragma unroll
    for (int mt = 0; mt < 2; mt++)
#pragma unroll
        for (int nt = 0; nt < 4; nt++) {
            int t = M0 + wm * 32 + mt * 16 + lr;
            int d = wn * 32 + nt * 8 + lc2;
            float4 c = acc[mt][nt];
            *(float2*)(concat + ((size_t)(b * TT + t)) * DM + h * DK + d) =
                make_float2(c.x, c.y);
            *(float2*)(concat + ((size_t)(b * TT + t + 8)) * DM + h * DK + d) =
                make_float2(c.z, c.w);
        }
}

// ======================================================================
extern "C" void kernel_launch(void* const* d_in, const int* in_sizes, int n_in,
                              void* d_out, int out_size)
{
    const float* q    = (const float*)d_in[0];
    const float* k    = (const float*)d_in[1];
    const float* v    = (const float*)d_in[2];
    const float* pos  = (const float*)d_in[3];
    const int*   mask = (const int*)d_in[4];
    const float* Wq   = (const float*)d_in[5];
    const float* bq   = (const float*)d_in[6];
    const float* Wk   = (const float*)d_in[7];
    const float* bk   = (const float*)d_in[8];
    const float* Wv   = (const float*)d_in[9];
    const float* bv   = (const float*)d_in[10];
    const float* Wp   = (const float*)d_in[11];
    const float* pbu  = (const float*)d_in[12];
    const float* pbv  = (const float*)d_in[13];
    const float* Wo   = (const float*)d_in[14];
    const float* bo   = (const float*)d_in[15];

    float *qh, *kh, *vt, *pp, *cc;
    cudaGetSymbolAddress((void**)&qh, g_qh);
    cudaGetSymbolAddress((void**)&kh, g_kh);
    cudaGetSymbolAddress((void**)&vt, g_vt);
    cudaGetSymbolAddress((void**)&pp, g_p);
    cudaGetSymbolAddress((void**)&cc, g_concat);

    float* out  = (float*)d_out;
    float* attn = out + (size_t)BSZ * TT * DM;

    static bool attr_done = false;
    if (!attr_done) {
        cudaFuncSetAttribute(bd_tc, cudaFuncAttributeMaxDynamicSharedMemorySize, QK_SMEM);
        cudaFuncSetAttribute(scores_tc, cudaFuncAttributeMaxDynamicSharedMemorySize, QK_SMEM);
        attr_done = true;
    }

    dim3 blk512(512);
    dim3 blk256(256);

    // Q, K, V projections batched (z -> mode 0/1/2)
    QKVArgs qa;
    qa.A[0] = q;  qa.A[1] = k;  qa.A[2] = v;
    qa.B[0] = Wq; qa.B[1] = Wk; qa.B[2] = Wv;
    qa.bias[0] = bq; qa.bias[1] = bk; qa.bias[2] = bv;
    qa.C[0] = qh; qa.C[1] = kh; qa.C[2] = vt;
    gemm_pipe<<<dim3(8, 32, 3), blk256>>>(qa, DM, -1);

    // pos projection (mode 3)
    QKVArgs pa = {};
    pa.A[0] = pos; pa.B[0] = Wp; pa.bias[0] = nullptr; pa.C[0] = pp;
    gemm_pipe<<<dim3(8, 8, 1), blk256>>>(pa, DM, 3);

    // BD = (qh + pos_bias_v) @ p^T, written SHIFTED into g_bd
    bd_tc<<<dim3(8, 8, 64), blk256, QK_SMEM>>>(pbv);

    // raw scores + per-tile softmax partials
    scores_tc<<<dim3(8, 8, 64), blk512, QK_SMEM>>>(mask, attn, pbu);

    // combine partials -> per-row (max, 1/sum)
    combine_stats<<<dim3(BSZ * HH * TT / 256), blk256>>>();

    // normalize in place + PV -> concat
    pv_fused<<<dim3(1, 8, 64), blk256>>>(attn, cc);

    // output = concat @ Wo^T + bo (mode 0)
    QKVArgs oa = {};
    oa.A[0] = cc; oa.B[0] = Wo; oa.bias[0] = bo; oa.C[0] = out;
    gemm_pipe<<<dim3(8, 32, 1), blk256>>>(oa, DM, 0);
}

// round 16
// speedup vs baseline: 1.0046x; 1.0021x over previous
#include <cuda_runtime.h>
#include <cstdint>

#define BSZ 4
#define TT  1024
#define DM  1024
#define HH  16
#define DK  64
#define KPAD 20
#define STG (128 * KPAD)
#define KB 68
#define QK_SMEM (2 * 128 * KB * 4)

// ---- device scratch (alloc-free rule: __device__ globals) ----
__device__ float g_qh[BSZ * TT * DM];              // (b, t, h, d)
__device__ float g_kh[BSZ * TT * DM];              // (b, h, t, d)
__device__ float g_vt[BSZ * TT * DM];              // (b, h, d, t)
__device__ float g_p[TT * DM];                     // (h, t, d)
__device__ float g_bd[67108864];                   // SHIFTED bd (b,h,t,s)
__device__ float g_concat[BSZ * TT * DM];          // (b, t, h*d)
__device__ float2 g_part[BSZ * HH * TT * 8];       // per-(row, colTile) (max, sumexp)
__device__ float2 g_ms[BSZ * HH * TT];             // per-row (max, 1/sum)

// ---------------------------------------------------------------
__device__ __forceinline__ float to_tf32(float x) {
    uint32_t u;
    asm("cvt.rna.tf32.f32 %0, %1;" : "=r"(u) : "f"(x));
    return __uint_as_float(u);
}
__device__ __forceinline__ uint32_t tf32u(float x) {
    uint32_t u;
    asm("cvt.rna.tf32.f32 %0, %1;" : "=r"(u) : "f"(x));
    return u;
}

__device__ __forceinline__ void mma8(float4& d, const uint32_t a[4], const uint32_t b[2]) {
    asm volatile(
        "mma.sync.aligned.m16n8k8.row.col.f32.tf32.tf32.f32 "
        "{%0,%1,%2,%3}, {%4,%5,%6,%7}, {%8,%9}, {%0,%1,%2,%3};\n"
        : "+f"(d.x), "+f"(d.y), "+f"(d.z), "+f"(d.w)
        : "r"(a[0]), "r"(a[1]), "r"(a[2]), "r"(a[3]), "r"(b[0]), "r"(b[1]));
}

__device__ __forceinline__ void cpa16(uint32_t saddr, const float* g) {
    asm volatile("cp.async.ca.shared.global [%0], [%1], 16;\n" :: "r"(saddr), "l"(g));
}
__device__ __forceinline__ void cp_commit() {
    asm volatile("cp.async.commit_group;\n");
}
template <int N>
__device__ __forceinline__ void cp_wait() {
    asm volatile("cp.async.wait_group %0;\n" :: "n"(N));
}

struct QKVArgs {
    const float* A[3];
    const float* B[3];
    const float* bias[3];
    float* C[3];
};

// ======================================================================
// Pipelined tensor-core NT GEMM — 256-thread (best measured)
// ======================================================================
__global__ __launch_bounds__(256, 2) void gemm_pipe(QKVArgs args, int K, int mode_sel)
{
    __shared__ __align__(16) float As[2 * STG];
    __shared__ __align__(16) float Bs[2 * STG];
    int z = blockIdx.z;
    int mode = (mode_sel >= 0) ? mode_sel : z;
    const float* A = args.A[z];
    const float* B = args.B[z];
    const float* bias = args.bias[z];
    float* C = args.C[z];
    bool has_bias = (bias != nullptr);

    int tid = threadIdx.x;
    int M0 = blockIdx.y * 128, N0 = blockIdx.x * 128;
    int w = tid >> 5, lane = tid & 31;
    int wm = w & 3, wn = w >> 2;
    int r = tid >> 2, c4 = (tid & 3) * 4;

    float4 acc[2][8];
#pragma unroll
    for (int i = 0; i < 2; i++)
#pragma unroll
        for (int j = 0; j < 8; j++) acc[i][j] = make_float4(0.f, 0.f, 0.f, 0.f);

    const float* Ag = A + (size_t)(M0 + r) * K + c4;
    const float* Bg = B + (size_t)(N0 + r) * K + c4;
    uint32_t sA = (uint32_t)__cvta_generic_to_shared(As);
    uint32_t sB = (uint32_t)__cvta_generic_to_shared(Bs);
    uint32_t offA0 = (r * KPAD + c4) * 4;
    uint32_t offA1 = ((r + 64) * KPAD + c4) * 4;

    cpa16(sA + offA0, Ag);
    cpa16(sA + offA1, Ag + (size_t)64 * K);
    cpa16(sB + offA0, Bg);
    cpa16(sB + offA1, Bg + (size_t)64 * K);
    cp_commit();

    int KT = K >> 4;
    for (int kt = 0; kt < KT; kt++) {
        if (kt + 1 < KT) {
            int st = (kt + 1) & 1;
            int k0 = (kt + 1) << 4;
            cpa16(sA + st * STG * 4 + offA0, Ag + k0);
            cpa16(sA + st * STG * 4 + offA1, Ag + (size_t)64 * K + k0);
            cpa16(sB + st * STG * 4 + offA0, Bg + k0);
            cpa16(sB + st * STG * 4 + offA1, Bg + (size_t)64 * K + k0);
            cp_commit();
            cp_wait<1>();
        } else {
            cp_wait<0>();
        }
        __syncthreads();
        const float* as = As + (kt & 1) * STG;
        const float* bs = Bs + (kt & 1) * STG;
#pragma unroll
        for (int ks = 0; ks < 16; ks += 8) {
            uint32_t bf[8][2];
#pragma unroll
            for (int nt = 0; nt < 8; nt++) {
                int nb = wn * 64 + nt * 8 + (lane >> 2);
                bf[nt][0] = tf32u(bs[nb * KPAD + ks + (lane & 3)]);
                bf[nt][1] = tf32u(bs[nb * KPAD + ks + (lane & 3) + 4]);
            }
#pragma unroll
            for (int mt = 0; mt < 2; mt++) {
                int mb = wm * 32 + mt * 16 + (lane >> 2);
                uint32_t af[4];
                af[0] = tf32u(as[mb * KPAD + ks + (lane & 3)]);
                af[1] = tf32u(as[(mb + 8) * KPAD + ks + (lane & 3)]);
                af[2] = tf32u(as[mb * KPAD + ks + (lane & 3) + 4]);
                af[3] = tf32u(as[(mb + 8) * KPAD + ks + (lane & 3) + 4]);
#pragma unroll
                for (int nt = 0; nt < 8; nt++) mma8(acc[mt][nt], af, bf[nt]);
            }
        }
        __syncthreads();
    }

    int lr = lane >> 2, lc2 = (lane & 3) * 2;
#pragma unroll
    for (int mt = 0; mt < 2; mt++) {
#pragma unroll
        for (int nt = 0; nt < 8; nt++) {
            int m = M0 + wm * 32 + mt * 16 + lr;
            int n = N0 + wn * 64 + nt * 8 + lc2;
            float b0 = has_bias ? bias[n] : 0.0f;
            float b1 = has_bias ? bias[n + 1] : 0.0f;
            float4 c = acc[mt][nt];
#pragma unroll
            for (int half = 0; half < 2; half++) {
                int mm = m + half * 8;
                float v0 = (half ? c.z : c.x) + b0;
                float v1 = (half ? c.w : c.y) + b1;
                if (mode == 0) {
                    *(float2*)(C + (size_t)mm * DM + n) = make_float2(v0, v1);
                } else if (mode == 1) {
                    int b = mm >> 10, s = mm & 1023;
                    int h = n >> 6, d = n & 63;
                    size_t idx = ((size_t)(b * HH + h) * TT + s) * DK + d;
                    *(float2*)(C + idx) = make_float2(v0, v1);
                } else if (mode == 2) {
                    int b = mm >> 10, s = mm & 1023;
                    int h = n >> 6, d = n & 63;
                    size_t idx = ((size_t)(b * HH + h) * DK + d) * TT + s;
                    C[idx] = v0;
                    C[idx + TT] = v1;
                } else { // mode 3
                    int h = n >> 6, d = n & 63;
                    size_t idx = ((size_t)h * TT + mm) * DK + d;
                    *(float2*)(C + idx) = make_float2(v0, v1);
                }
            }
        }
    }
}

// ======================================================================
// BD scatter: raw (m,n) -> shifted layout (scalar: alignment-hostile).
// ======================================================================
__device__ __forceinline__ void bd_scatter(float* out, int m, int n, float v)
{
    if (n >= TT - 1 - m) {
        out[(size_t)m * TT + (n - TT + 1 + m)] = v;
        if (m >= 1 && n == TT - 1 - m) out[(size_t)(m - 1) * TT + m] = 0.0f;
    } else if (m >= 1) {
        out[(size_t)(m - 1) * TT + (n + m + 1)] = v;
    }
}

// ======================================================================
// BD kernel — 256 threads, SINGLE-SHOT K=64 smem staging (1 barrier).
// ======================================================================
__global__ __launch_bounds__(256, 2) void bd_tc(const float* __restrict__ posb)
{
    extern __shared__ __align__(16) float dsm[];
    float* As = dsm;                 // 128 x KB
    float* Bs = dsm + 128 * KB;      // 128 x KB
    int bh = blockIdx.z;
    int b = bh >> 4, h = bh & 15;
    int tid = threadIdx.x;
    int M0 = blockIdx.y * 128, N0 = blockIdx.x * 128;
    int w = tid >> 5, lane = tid & 31;
    int wm = w & 3, wn = w >> 2;

    const float* Ab = g_qh + (size_t)b * TT * DM + h * DK;
    const float* Bb = g_p + (size_t)h * TT * DK;
    const float* pb = posb + h * DK;

    // load whole 128x64 A and B tiles (8 float4 per thread per tile)
    int r0 = tid >> 4;               // 0..15
    int c4 = (tid & 15) * 4;         // 0..60
    float4 pv = *(const float4*)(pb + c4);
#pragma unroll
    for (int i = 0; i < 8; i++) {
        int row = r0 + i * 16;
        float4 va = *(const float4*)(Ab + (size_t)(M0 + row) * DM + c4);
        float4 vb = *(const float4*)(Bb + (size_t)(N0 + row) * DK + c4);
        *(float4*)&As[row * KB + c4] = make_float4(
            to_tf32(va.x + pv.x), to_tf32(va.y + pv.y),
            to_tf32(va.z + pv.z), to_tf32(va.w + pv.w));
        *(float4*)&Bs[row * KB + c4] =
            make_float4(to_tf32(vb.x), to_tf32(vb.y), to_tf32(vb.z), to_tf32(vb.w));
    }
    __syncthreads();

    float4 acc[2][8];
#pragma unroll
    for (int i = 0; i < 2; i++)
#pragma unroll
        for (int j = 0; j < 8; j++) acc[i][j] = make_float4(0.f, 0.f, 0.f, 0.f);

#pragma unroll
    for (int ks = 0; ks < 64; ks += 8) {
        uint32_t bf[8][2];
#pragma unroll
        for (int nt = 0; nt < 8; nt++) {
            int nb = wn * 64 + nt * 8 + (lane >> 2);
            bf[nt][0] = __float_as_uint(Bs[nb * KB + ks + (lane & 3)]);
            bf[nt][1] = __float_as_uint(Bs[nb * KB + ks + (lane & 3) + 4]);
        }
#pragma unroll
        for (int mt = 0; mt < 2; mt++) {
            int mb = wm * 32 + mt * 16 + (lane >> 2);
            uint32_t af[4];
            af[0] = __float_as_uint(As[mb * KB + ks + (lane & 3)]);
            af[1] = __float_as_uint(As[(mb + 8) * KB + ks + (lane & 3)]);
            af[2] = __float_as_uint(As[mb * KB + ks + (lane & 3) + 4]);
            af[3] = __float_as_uint(As[(mb + 8) * KB + ks + (lane & 3) + 4]);
#pragma unroll
            for (int nt = 0; nt < 8; nt++) mma8(acc[mt][nt], af, bf[nt]);
        }
    }

    float* out = g_bd + (size_t)bh * TT * TT;
    int lr = lane >> 2, lc2 = (lane & 3) * 2;
#pragma unroll
    for (int mt = 0; mt < 2; mt++)
#pragma unroll
        for (int nt = 0; nt < 8; nt++) {
            int m = M0 + wm * 32 + mt * 16 + lr;
            int n = N0 + wn * 64 + nt * 8 + lc2;
            float4 c = acc[mt][nt];
            bd_scatter(out, m,     n,     c.x);
            bd_scatter(out, m,     n + 1, c.y);
            bd_scatter(out, m + 8, n,     c.z);
            bd_scatter(out, m + 8, n + 1, c.w);
        }
}

// ======================================================================
// Scores — 512 threads, SINGLE-SHOT K=64 staging (1 barrier in mainloop),
// wide shfl-regrouped epilogue + online softmax partials.
// ======================================================================
__global__ __launch_bounds__(512, 2) void scores_tc(
    const int* __restrict__ mask, float* __restrict__ outp,
    const float* __restrict__ posb)
{
    extern __shared__ __align__(16) float dsm[];
    float* As = dsm;
    float* Bs = dsm + 128 * KB;
    __shared__ float2 sred[128][4];
    int bh = blockIdx.z;
    int b = bh >> 4, h = bh & 15;
    int tid = threadIdx.x;
    int M0 = blockIdx.y * 128, N0 = blockIdx.x * 128;
    int w = tid >> 5, lane = tid & 31;
    int wm = w & 3, wn = w >> 2;
    int lr = lane >> 2, lc = lane & 3;

    const float* Ab = g_qh + (size_t)b * TT * DM + h * DK;
    const float* Bb = g_kh + (size_t)bh * TT * DK;
    const float* pb = posb + h * DK;

    // load whole 128x64 tiles (4 float4 per thread per tile)
    int r0 = tid >> 4;               // 0..31
    int c4 = (tid & 15) * 4;
    float4 pv = *(const float4*)(pb + c4);
#pragma unroll
    for (int i = 0; i < 4; i++) {
        int row = r0 + i * 32;
        float4 va = *(const float4*)(Ab + (size_t)(M0 + row) * DM + c4);
        float4 vb = *(const float4*)(Bb + (size_t)(N0 + row) * DK + c4);
        *(float4*)&As[row * KB + c4] = make_float4(
            to_tf32(va.x + pv.x), to_tf32(va.y + pv.y),
            to_tf32(va.z + pv.z), to_tf32(va.w + pv.w));
        *(float4*)&Bs[row * KB + c4] =
            make_float4(to_tf32(vb.x), to_tf32(vb.y), to_tf32(vb.z), to_tf32(vb.w));
    }
    __syncthreads();

    float4 acc[2][4];
#pragma unroll
    for (int i = 0; i < 2; i++)
#pragma unroll
        for (int j = 0; j < 4; j++) acc[i][j] = make_float4(0.f, 0.f, 0.f, 0.f);

#pragma unroll
    for (int ks = 0; ks < 64; ks += 8) {
        uint32_t bf[4][2];
#pragma unroll
        for (int nt = 0; nt < 4; nt++) {
            int nb = wn * 32 + nt * 8 + lr;
            bf[nt][0] = __float_as_uint(Bs[nb * KB + ks + lc]);
            bf[nt][1] = __float_as_uint(Bs[nb * KB + ks + lc + 4]);
        }
#pragma unroll
        for (int mt = 0; mt < 2; mt++) {
            int mb = wm * 32 + mt * 16 + lr;
            uint32_t af[4];
            af[0] = __float_as_uint(As[mb * KB + ks + lc]);
            af[1] = __float_as_uint(As[(mb + 8) * KB + ks + lc]);
            af[2] = __float_as_uint(As[mb * KB + ks + lc + 4]);
            af[3] = __float_as_uint(As[(mb + 8) * KB + ks + lc + 4]);
#pragma unroll
            for (int nt = 0; nt < 4; nt++) mma8(acc[mt][nt], af, bf[nt]);
        }
    }

    const float* BD = g_bd + (size_t)bh * TT * TT;
    const int* mk = mask + (size_t)b * TT * TT;
    float* out = outp + (size_t)bh * TT * TT;

    // shfl-regrouped epilogue
    int rowoff = (lc & 1) * 8;
    int colgrp = (lc & 2) * 2;
#pragma unroll
    for (int mt = 0; mt < 2; mt++) {
        int rbase = wm * 32 + mt * 16 + lr;
        int a = M0 + rbase + rowoff;
        float4 sv[4];
        float mloc = -1e30f;
#pragma unroll
        for (int nt = 0; nt < 4; nt++) {
            int n = N0 + wn * 32 + nt * 8 + colgrp;
            float4 c = acc[mt][nt];
            float px = __shfl_xor_sync(0xffffffffu, c.x, 1);
            float py = __shfl_xor_sync(0xffffffffu, c.y, 1);
            float pz = __shfl_xor_sync(0xffffffffu, c.z, 1);
            float pw = __shfl_xor_sync(0xffffffffu, c.w, 1);
            float4 v = (lc & 1) ? make_float4(pz, pw, c.z, c.w)
                                : make_float4(c.x, c.y, px, py);
            float4 bd4 = *(const float4*)(BD + (size_t)a * TT + n);
            int4 mv = *(const int4*)(mk + (size_t)a * TT + n);
            float4 s;
            s.x = (v.x + bd4.x) * 0.125f; if (mv.x == 0) s.x = -10000.0f;
            s.y = (v.y + bd4.y) * 0.125f; if (mv.y == 0) s.y = -10000.0f;
            s.z = (v.z + bd4.z) * 0.125f; if (mv.z == 0) s.z = -10000.0f;
            s.w = (v.w + bd4.w) * 0.125f; if (mv.w == 0) s.w = -10000.0f;
            __stcs((float4*)(out + (size_t)a * TT + n), s);
            sv[nt] = s;
            mloc = fmaxf(mloc, fmaxf(fmaxf(s.x, s.y), fmaxf(s.z, s.w)));
        }
        float ssum = 0.0f;
#pragma unroll
        for (int nt = 0; nt < 4; nt++) {
            ssum += __expf(sv[nt].x - mloc) + __expf(sv[nt].y - mloc)
                  + __expf(sv[nt].z - mloc) + __expf(sv[nt].w - mloc);
        }
        float mo = __shfl_xor_sync(0xffffffffu, mloc, 2);
        float so = __shfl_xor_sync(0xffffffffu, ssum, 2);
        float M2 = fmaxf(mloc, mo);
        ssum = ssum * __expf(mloc - M2) + so * __expf(mo - M2);
        mloc = M2;
        if (lc < 2) sred[rbase + lc * 8][wn] = make_float2(mloc, ssum);
    }
    __syncthreads();
    if (tid < 128) {
        float2 q = sred[tid][0];
        float M = q.x, S = q.y;
#pragma unroll
        for (int j = 1; j < 4; j++) {
            float2 qq = sred[tid][j];
            float M2 = fmaxf(M, qq.x);
            S = S * __expf(M - M2) + qq.y * __expf(qq.x - M2);
            M = M2;
        }
        g_part[((size_t)bh * TT + M0 + tid) * 8 + (N0 >> 7)] = make_float2(M, S);
    }
}

// ======================================================================
// Combine per-tile partials -> per-row (max, 1/sum)
// ======================================================================
__global__ __launch_bounds__(256) void combine_stats()
{
    int idx = blockIdx.x * 256 + threadIdx.x;
    const float2* p = g_part + (size_t)idx * 8;
    float2 q = p[0];
    float M = q.x, S = q.y;
#pragma unroll
    for (int j = 1; j < 8; j++) {
        float2 qq = p[j];
        float M2 = fmaxf(M, qq.x);
        S = S * __expf(M - M2) + qq.y * __expf(qq.x - M2);
        M = M2;
    }
    g_ms[idx] = make_float2(M, 1.0f / S);
}

// ======================================================================
// PV fused — R8 256-thread version (measured best).
// ======================================================================
__global__ __launch_bounds__(256, 2) void pv_fused(
    float* __restrict__ attn, float* __restrict__ concat)
{
    __shared__ __align__(16) float As[128 * KPAD];
    __shared__ __align__(16) float Bs[2 * 64 * KPAD];
    int bh = blockIdx.z;
    int b = bh >> 4, h = bh & 15;
    int tid = threadIdx.x;
    int M0 = blockIdx.y * 128;
    int w = tid >> 5, lane = tid & 31;
    int wm = w & 3, wn = w >> 2;
    int r = tid >> 2, c4 = (tid & 3) * 4;

    float* Ag = attn + (size_t)bh * TT * TT + (size_t)(M0 + r) * TT + c4;
    const float* Bg = g_vt + (size_t)bh * DK * TT + (size_t)r * TT + c4;
    uint32_t sB = (uint32_t)__cvta_generic_to_shared(Bs);
    uint32_t offB = (r * KPAD + c4) * 4;

    float2 ms0 = g_ms[(size_t)bh * TT + M0 + r];
    float2 ms1 = g_ms[(size_t)bh * TT + M0 + r + 64];

    float4 acc[2][4];
#pragma unroll
    for (int i = 0; i < 2; i++)
#pragma unroll
        for (int j = 0; j < 4; j++) acc[i][j] = make_float4(0.f, 0.f, 0.f, 0.f);

    float4 ra0 = *(const float4*)(Ag);
    float4 ra1 = *(const float4*)(Ag + (size_t)64 * TT);
    cpa16(sB + offB, Bg);
    cp_commit();

    const int KT = TT >> 4;
    for (int kt = 0; kt < KT; kt++) {
        int k0 = kt << 4;
        float4 p0, p1;
        p0.x = __expf(ra0.x - ms0.x) * ms0.y;
        p0.y = __expf(ra0.y - ms0.x) * ms0.y;
        p0.z = __expf(ra0.z - ms0.x) * ms0.y;
        p0.w = __expf(ra0.w - ms0.x) * ms0.y;
        p1.x = __expf(ra1.x - ms1.x) * ms1.y;
        p1.y = __expf(ra1.y - ms1.x) * ms1.y;
        p1.z = __expf(ra1.z - ms1.x) * ms1.y;
        p1.w = __expf(ra1.w - ms1.x) * ms1.y;
        __stcs((float4*)(Ag + k0), p0);
        __stcs((float4*)(Ag + (size_t)64 * TT + k0), p1);
        *(float4*)&As[r * KPAD + c4] =
            make_float4(to_tf32(p0.x), to_tf32(p0.y), to_tf32(p0.z), to_tf32(p0.w));
        *(float4*)&As[(r + 64) * KPAD + c4] =
            make_float4(to_tf32(p1.x), to_tf32(p1.y), to_tf32(p1.z), to_tf32(p1.w));

        if (kt + 1 < KT) {
            int k0n = (kt + 1) << 4;
            ra0 = *(const float4*)(Ag + k0n);
            ra1 = *(const float4*)(Ag + (size_t)64 * TT + k0n);
            cpa16(sB + ((kt + 1) & 1) * 64 * KPAD * 4 + offB, Bg + k0n);
            cp_commit();
            cp_wait<1>();
        } else {
            cp_wait<0>();
        }
        __syncthreads();

        const float* bs = Bs + (kt & 1) * 64 * KPAD;
#pragma unroll
        for (int ks = 0; ks < 16; ks += 8) {
            uint32_t bf[4][2];
#pragma unroll
            for (int nt = 0; nt < 4; nt++) {
                int nb = wn * 32 + nt * 8 + (lane >> 2);
                bf[nt][0] = tf32u(bs[nb * KPAD + ks + (lane & 3)]);
                bf[nt][1] = tf32u(bs[nb * KPAD + ks + (lane & 3) + 4]);
            }
#pragma unroll
            for (int mt = 0; mt < 2; mt++) {
                int mb = wm * 32 + mt * 16 + (lane >> 2);
                uint32_t af[4];
                af[0] = __float_as_uint(As[mb * KPAD + ks + (lane & 3)]);
                af[1] = __float_as_uint(As[(mb + 8) * KPAD + ks + (lane & 3)]);
                af[2] = __float_as_uint(As[mb * KPAD + ks + (lane & 3) + 4]);
                af[3] = __float_as_uint(As[(mb + 8) * KPAD + ks + (lane & 3) + 4]);
#pragma unroll
                for (int nt = 0; nt < 4; nt++) mma8(acc[mt][nt], af, bf[nt]);
            }
        }
        __syncthreads();
    }

    int lr = lane >> 2, lc2 = (lane & 3) * 2;
#pragma unroll
    for (int mt = 0; mt < 2; mt++)
#pragma unroll
        for (int nt = 0; nt < 4; nt++) {
            int t = M0 + wm * 32 + mt * 16 + lr;
            int d = wn * 32 + nt * 8 + lc2;
            float4 c = acc[mt][nt];
            *(float2*)(concat + ((size_t)(b * TT + t)) * DM + h * DK + d) =
                make_float2(c.x, c.y);
            *(float2*)(concat + ((size_t)(b * TT + t + 8)) * DM + h * DK + d) =
                make_float2(c.z, c.w);
        }
}

// ======================================================================
extern "C" void kernel_launch(void* const* d_in, const int* in_sizes, int n_in,
                              void* d_out, int out_size)
{
    const float* q    = (const float*)d_in[0];
    const float* k    = (const float*)d_in[1];
    const float* v    = (const float*)d_in[2];
    const float* pos  = (const float*)d_in[3];
    const int*   mask = (const int*)d_in[4];
    const float* Wq   = (const float*)d_in[5];
    const float* bq   = (const float*)d_in[6];
    const float* Wk   = (const float*)d_in[7];
    const float* bk   = (const float*)d_in[8];
    const float* Wv   = (const float*)d_in[9];
    const float* bv   = (const float*)d_in[10];
    const float* Wp   = (const float*)d_in[11];
    const float* pbu  = (const float*)d_in[12];
    const float* pbv  = (const float*)d_in[13];
    const float* Wo   = (const float*)d_in[14];
    const float* bo   = (const float*)d_in[15];

    float *qh, *kh, *vt, *pp, *cc;
    cudaGetSymbolAddress((void**)&qh, g_qh);
    cudaGetSymbolAddress((void**)&kh, g_kh);
    cudaGetSymbolAddress((void**)&vt, g_vt);
    cudaGetSymbolAddress((void**)&pp, g_p);
    cudaGetSymbolAddress((void**)&cc, g_concat);

    float* out  = (float*)d_out;
    float* attn = out + (size_t)BSZ * TT * DM;

    static bool attr_done = false;
    if (!attr_done) {
        cudaFuncSetAttribute(bd_tc, cudaFuncAttributeMaxDynamicSharedMemorySize, QK_SMEM);
        cudaFuncSetAttribute(scores_tc, cudaFuncAttributeMaxDynamicSharedMemorySize, QK_SMEM);
        attr_done = true;
    }

    dim3 blk512(512);
    dim3 blk256(256);

    // Q, K, V projections batched (z -> mode 0/1/2)
    QKVArgs qa;
    qa.A[0] = q;  qa.A[1] = k;  qa.A[2] = v;
    qa.B[0] = Wq; qa.B[1] = Wk; qa.B[2] = Wv;
    qa.bias[0] = bq; qa.bias[1] = bk; qa.bias[2] = bv;
    qa.C[0] = qh; qa.C[1] = kh; qa.C[2] = vt;
    gemm_pipe<<<dim3(8, 32, 3), blk256>>>(qa, DM, -1);

    // pos projection (mode 3)
    QKVArgs pa = {};
    pa.A[0] = pos; pa.B[0] = Wp; pa.bias[0] = nullptr; pa.C[0] = pp;
    gemm_pipe<<<dim3(8, 8, 1), blk256>>>(pa, DM, 3);

    // BD = (qh + pos_bias_v) @ p^T, written SHIFTED into g_bd
    bd_tc<<<dim3(8, 8, 64), blk256, QK_SMEM>>>(pbv);

    // raw scores + per-tile softmax partials
    scores_tc<<<dim3(8, 8, 64), blk512, QK_SMEM>>>(mask, attn, pbu);

    // combine partials -> per-row (max, 1/sum)
    combine_stats<<<dim3(BSZ * HH * TT / 256), blk256>>>();

    // normalize in place + PV -> concat
    pv_fused<<<dim3(1, 8, 64), blk256>>>(attn, cc);

    // output = concat @ Wo^T + bo (mode 0)
    QKVArgs oa = {};
    oa.A[0] = cc; oa.B[0] = Wo; oa.bias[0] = bo; oa.C[0] = out;
    gemm_pipe<<<dim3(8, 32, 1), blk256>>>(oa, DM, 0);
}